// round 14
// baseline (speedup 1.0000x reference)
#include <cuda_runtime.h>

typedef unsigned long long u64;

#define B_TOT 2048
#define T_LEN 512
#define IN_SZ 20
#define H     64
#define BTILE 16
#define NTHR  512

// ---- smem layout (float offsets) ----
#define OFF_W0   0                  // whh0^T  [64 j][64 u][4 g] = 16384
#define OFF_W1I  16384
#define OFF_W1H  32768
#define OFF_H0   49152              // h0 [2 buf][64 u][20 (16 used)] = 2560
#define OFF_H1   51712              // h1 [2][64][20] = 2560
#define OFF_XS   54272              // x  [2][20 k][16 b] = 640
#define SMEM_FLOATS 54912
#define SMEM_BYTES  (SMEM_FLOATS*4) // 219648 B

__device__ __forceinline__ u64 dup2(float v){ u64 r; asm("mov.b64 %0,{%1,%1};":"=l"(r):"f"(v)); return r; }
__device__ __forceinline__ void fma2(u64& d, u64 a, u64 b){ asm("fma.rn.f32x2 %0,%1,%2,%0;":"+l"(d):"l"(a),"l"(b)); }
__device__ __forceinline__ u64 add2(u64 a, u64 b){ u64 r; asm("add.rn.f32x2 %0,%1,%2;":"=l"(r):"l"(a),"l"(b)); return r; }
__device__ __forceinline__ void unpk(u64 v, float& lo, float& hi){ asm("mov.b64 {%0,%1},%2;":"=f"(lo),"=f"(hi):"l"(v)); }

__device__ __forceinline__ float sigmoid_f(float v){ return 1.0f/(1.0f+__expf(-v)); }
__device__ __forceinline__ float tanh_f(float v){
    float xx = fmaxf(v, -15.0f);
    float t  = __expf(-2.0f*xx);
    return __fdividef(1.0f - t, 1.0f + t);
}

__global__ void __launch_bounds__(NTHR,1) lstm2_kernel(
    const float* __restrict__ x,
    const float* __restrict__ w_ih0, const float* __restrict__ w_hh0,
    const float* __restrict__ b_ih0, const float* __restrict__ b_hh0,
    const float* __restrict__ w_ih1, const float* __restrict__ w_hh1,
    const float* __restrict__ b_ih1, const float* __restrict__ b_hh1,
    const float* __restrict__ w_out, const float* __restrict__ b_out,
    float* __restrict__ out)
{
    extern __shared__ float sm[];
    float* W0  = sm + OFF_W0;
    float* W1I = sm + OFF_W1I;
    float* W1H = sm + OFF_W1H;
    float* h0b = sm + OFF_H0;
    float* h1b = sm + OFF_H1;
    float* xsm = sm + OFF_XS;

    const int tid    = threadIdx.x;
    const int lane   = tid & 31;
    const int wid    = tid >> 5;
    const int ul     = lane & 7;
    const int bgl    = (lane >> 3) & 1;
    const int kh     = lane >> 4;          // K-half, intra-warp (bit 4)
    const int uh     = wid & 7;
    const int bgo    = wid >> 3;
    const int u      = uh * 8 + ul;        // hidden unit
    const int g4     = bgo * 2 + bgl;      // 4-batch group 0..3
    const int bown   = g4 * 4 + kh * 2;    // first owned batch (local in tile)
    const int batch0 = blockIdx.x * BTILE;

    // ---- weight transpose into smem: dst[(j*64+u)*4 + gate] ----
    for (int idx = tid; idx < 4*H*H; idx += NTHR) {
        int g = idx >> 6, j = idx & 63;
        int dst = ((j << 6) + (g & 63)) * 4 + (g >> 6);
        W0 [dst] = w_hh0[idx];
        W1I[dst] = w_ih1[idx];
        W1H[dst] = w_hh1[idx];
    }
    // zero h buffers (contiguous 5120 floats)
    for (int idx = tid; idx < 5120; idx += NTHR) h0b[idx] = 0.0f;
    // x t=0 into buffer 0 ([k][b])
    if (tid < BTILE*IN_SZ) {
        int b = tid / IN_SZ, k = tid - b*IN_SZ;
        xsm[k*16 + b] = x[(batch0 + b) * (T_LEN*IN_SZ) + k];
    }

    // per-thread w_ih0 rows: this u's 4 gates, its interleaved K-half (k = 2kk+kh)
    float w0r[4][10];
#pragma unroll
    for (int m = 0; m < 4; m++)
#pragma unroll
        for (int kk = 0; kk < 10; kk++)
            w0r[m][kk] = w_ih0[(m*64 + u)*IN_SZ + 2*kk + kh];

    float bs0[4], bs1[4];
#pragma unroll
    for (int m = 0; m < 4; m++) {
        bs0[m] = b_ih0[m*64 + u] + b_hh0[m*64 + u];
        bs1[m] = b_ih1[m*64 + u] + b_hh1[m*64 + u];
    }
    float c0[2] = {0.f, 0.f}, c1[2] = {0.f, 0.f};

    // x prefetch mapping
    const bool xth = tid < BTILE*IN_SZ;
    const int  xb  = xth ? tid / IN_SZ : 0;
    const int  xk  = xth ? tid - xb*IN_SZ : 0;

    __syncthreads();

    for (int t = 0; t < T_LEN; t++) {
        const int cur = t & 1, prv = cur ^ 1;

        float xpre = 0.0f;
        if (xth && t + 1 < T_LEN)
            xpre = x[(batch0 + xb)*(T_LEN*IN_SZ) + (t+1)*IN_SZ + xk];

        const float* h0r = h0b + prv*1280;

        // ================= layer 0 gates =================
        u64 a0[4] = {0,0,0,0}, a1[4] = {0,0,0,0};   // mem-pair0 / mem-pair1

        // x part: k = 2kk + kh
#pragma unroll
        for (int kk = 0; kk < 10; kk++) {
            ulonglong2 xv = *(const ulonglong2*)(xsm + cur*320 + (2*kk + kh)*16 + g4*4);
#pragma unroll
            for (int m = 0; m < 4; m++) {
                u64 w = dup2(w0r[m][kk]);
                fma2(a0[m], w, xv.x);
                fma2(a1[m], w, xv.y);
            }
        }
        // h part: j = 2*j0 + kh
#pragma unroll 8
        for (int j0 = 0; j0 < 32; j0++) {
            int j = 2*j0 + kh;
            float4 w4 = *(const float4*)(W0 + (j << 8) + (u << 2));
            ulonglong2 hv = *(const ulonglong2*)(h0r + j*20 + g4*4);
            u64 p0 = dup2(w4.x), p1 = dup2(w4.y), p2 = dup2(w4.z), p3 = dup2(w4.w);
            fma2(a0[0],p0,hv.x); fma2(a1[0],p0,hv.y);
            fma2(a0[1],p1,hv.x); fma2(a1[1],p1,hv.y);
            fma2(a0[2],p2,hv.x); fma2(a1[2],p2,hv.y);
            fma2(a0[3],p3,hv.x); fma2(a1[3],p3,hv.y);
        }
        // shuffle K-reduce: own = owned mem-pair (index kh), partner holds other K-half
        {
            float hn0, hn1;
            float pre[4][2];
#pragma unroll
            for (int m = 0; m < 4; m++) {
                u64 own = kh ? a1[m] : a0[m];
                u64 oth = kh ? a0[m] : a1[m];
                u64 r = __shfl_xor_sync(0xffffffffu, oth, 16);
                own = add2(own, r);
                unpk(own, pre[m][0], pre[m][1]);
            }
#pragma unroll
            for (int s = 0; s < 2; s++) {
                float iv = sigmoid_f(pre[0][s] + bs0[0]);
                float fv = sigmoid_f(pre[1][s] + bs0[1]);
                float gv = tanh_f   (pre[2][s] + bs0[2]);
                float ov = sigmoid_f(pre[3][s] + bs0[3]);
                float c  = fmaf(fv, c0[s], iv * gv);
                c0[s] = c;
                float hv2 = ov * tanh_f(c);
                if (s == 0) hn0 = hv2; else hn1 = hv2;
            }
            *(float2*)(h0b + cur*1280 + u*20 + bown) = make_float2(hn0, hn1);
        }
        __syncthreads();    // h0(t) ready

        const float* h0n = h0b + cur*1280;
        const float* h1r = h1b + prv*1280;

        // ================= layer 1 gates =================
#pragma unroll
        for (int m = 0; m < 4; m++) { a0[m] = 0ull; a1[m] = 0ull; }

#pragma unroll 4
        for (int j0 = 0; j0 < 32; j0++) {
            int j = 2*j0 + kh;
            float4 wa = *(const float4*)(W1I + (j << 8) + (u << 2));
            float4 wb = *(const float4*)(W1H + (j << 8) + (u << 2));
            ulonglong2 ha = *(const ulonglong2*)(h0n + j*20 + g4*4);
            ulonglong2 hb = *(const ulonglong2*)(h1r + j*20 + g4*4);
            {
                u64 p0 = dup2(wa.x), p1 = dup2(wa.y), p2 = dup2(wa.z), p3 = dup2(wa.w);
                fma2(a0[0],p0,ha.x); fma2(a1[0],p0,ha.y);
                fma2(a0[1],p1,ha.x); fma2(a1[1],p1,ha.y);
                fma2(a0[2],p2,ha.x); fma2(a1[2],p2,ha.y);
                fma2(a0[3],p3,ha.x); fma2(a1[3],p3,ha.y);
            }
            {
                u64 p0 = dup2(wb.x), p1 = dup2(wb.y), p2 = dup2(wb.z), p3 = dup2(wb.w);
                fma2(a0[0],p0,hb.x); fma2(a1[0],p0,hb.y);
                fma2(a0[1],p1,hb.x); fma2(a1[1],p1,hb.y);
                fma2(a0[2],p2,hb.x); fma2(a1[2],p2,hb.y);
                fma2(a0[3],p3,hb.x); fma2(a1[3],p3,hb.y);
            }
        }
        {
            float hn0, hn1;
            float pre[4][2];
#pragma unroll
            for (int m = 0; m < 4; m++) {
                u64 own = kh ? a1[m] : a0[m];
                u64 oth = kh ? a0[m] : a1[m];
                u64 r = __shfl_xor_sync(0xffffffffu, oth, 16);
                own = add2(own, r);
                unpk(own, pre[m][0], pre[m][1]);
            }
#pragma unroll
            for (int s = 0; s < 2; s++) {
                float iv = sigmoid_f(pre[0][s] + bs1[0]);
                float fv = sigmoid_f(pre[1][s] + bs1[1]);
                float gv = tanh_f   (pre[2][s] + bs1[2]);
                float ov = sigmoid_f(pre[3][s] + bs1[3]);
                float c  = fmaf(fv, c1[s], iv * gv);
                c1[s] = c;
                float hv2 = ov * tanh_f(c);
                if (s == 0) hn0 = hv2; else hn1 = hv2;
            }
            *(float2*)(h1b + cur*1280 + u*20 + bown) = make_float2(hn0, hn1);
        }
        // commit prefetched x into the other buffer (read next step by layer 0)
        if (xth && t + 1 < T_LEN)
            xsm[prv*320 + xk*16 + xb] = xpre;
        __syncthreads();    // h1(t), x(t+1) ready
    }

    // ================= output projection (h1 final at buffer (T_LEN-1)&1 = 1) =================
    if (tid < BTILE*5) {
        int b = tid / 5, o = tid - 5*b;
        float s = b_out[o];
        const float* hr = h1b + 1280 + b;   // stride 20 per u
        const float* wr = w_out + o*H;
#pragma unroll 16
        for (int uu = 0; uu < H; uu++) s = fmaf(hr[uu*20], wr[uu], s);
        out[(batch0 + b)*5 + o] = s;
    }
}

extern "C" void kernel_launch(void* const* d_in, const int* in_sizes, int n_in,
                              void* d_out, int out_size) {
    const float* x     = (const float*)d_in[0];
    const float* w_ih0 = (const float*)d_in[1];
    const float* w_hh0 = (const float*)d_in[2];
    const float* b_ih0 = (const float*)d_in[3];
    const float* b_hh0 = (const float*)d_in[4];
    const float* w_ih1 = (const float*)d_in[5];
    const float* w_hh1 = (const float*)d_in[6];
    const float* b_ih1 = (const float*)d_in[7];
    const float* b_hh1 = (const float*)d_in[8];
    const float* w_out = (const float*)d_in[9];
    const float* b_out = (const float*)d_in[10];
    float* out = (float*)d_out;

    cudaFuncSetAttribute(lstm2_kernel, cudaFuncAttributeMaxDynamicSharedMemorySize, SMEM_BYTES);
    lstm2_kernel<<<B_TOT / BTILE, NTHR, SMEM_BYTES>>>(
        x, w_ih0, w_hh0, b_ih0, b_hh0,
        w_ih1, w_hh1, b_ih1, b_hh1,
        w_out, b_out, out);
}

// round 15
// speedup vs baseline: 1.0013x; 1.0013x over previous
#include <cuda_runtime.h>

typedef unsigned long long u64;

#define B_TOT 2048
#define T_LEN 512
#define IN_SZ 20
#define H     64
#define BTILE 16
#define NTHR  512

// ---- smem layout (float offsets) ----
#define OFF_W0   0                  // whh0^T  [64 j][64 u][4 g] = 16384
#define OFF_W1I  16384
#define OFF_W1H  32768
#define OFF_H0   49152              // h0 [2 buf][64 u][20 (16 used)] = 2560
#define OFF_H1   51712              // h1 [2][64][20] = 2560
#define OFF_XS   54272              // x  [2][20 k][16 b] = 640
#define SMEM_FLOATS 54912
#define SMEM_BYTES  (SMEM_FLOATS*4) // 219648 B

__device__ __forceinline__ u64 dup2(float v){ u64 r; asm("mov.b64 %0,{%1,%1};":"=l"(r):"f"(v)); return r; }
__device__ __forceinline__ void fma2(u64& d, u64 a, u64 b){ asm("fma.rn.f32x2 %0,%1,%2,%0;":"+l"(d):"l"(a),"l"(b)); }
__device__ __forceinline__ u64 add2(u64 a, u64 b){ u64 r; asm("add.rn.f32x2 %0,%1,%2;":"=l"(r):"l"(a),"l"(b)); return r; }
__device__ __forceinline__ void unpk(u64 v, float& lo, float& hi){ asm("mov.b64 {%0,%1},%2;":"=f"(lo),"=f"(hi):"l"(v)); }

__device__ __forceinline__ float sigmoid_f(float v){ return 1.0f/(1.0f+__expf(-v)); }
__device__ __forceinline__ float tanh_f(float v){
    float xx = fmaxf(v, -15.0f);
    float t  = __expf(-2.0f*xx);
    return __fdividef(1.0f - t, 1.0f + t);
}

__global__ void __launch_bounds__(NTHR,1) lstm2_kernel(
    const float* __restrict__ x,
    const float* __restrict__ w_ih0, const float* __restrict__ w_hh0,
    const float* __restrict__ b_ih0, const float* __restrict__ b_hh0,
    const float* __restrict__ w_ih1, const float* __restrict__ w_hh1,
    const float* __restrict__ b_ih1, const float* __restrict__ b_hh1,
    const float* __restrict__ w_out, const float* __restrict__ b_out,
    float* __restrict__ out)
{
    extern __shared__ float sm[];
    float* W0  = sm + OFF_W0;
    float* W1I = sm + OFF_W1I;
    float* W1H = sm + OFF_W1H;
    float* h0b = sm + OFF_H0;
    float* h1b = sm + OFF_H1;
    float* xsm = sm + OFF_XS;

    const int tid    = threadIdx.x;
    const int lane   = tid & 31;
    const int wid    = tid >> 5;
    const int ul     = lane & 7;
    const int bgl    = (lane >> 3) & 1;
    const int kh     = lane >> 4;          // K-half, intra-warp (bit 4)
    const int uh     = wid & 7;
    const int bgo    = wid >> 3;
    const int u      = uh * 8 + ul;        // hidden unit
    const int g4     = bgo * 2 + bgl;      // 4-batch group 0..3
    const int bown   = g4 * 4 + kh * 2;    // first owned batch (local in tile)
    const int batch0 = blockIdx.x * BTILE;

    // ---- weight transpose into smem: dst[(j*64+u)*4 + gate] ----
    for (int idx = tid; idx < 4*H*H; idx += NTHR) {
        int g = idx >> 6, j = idx & 63;
        int dst = ((j << 6) + (g & 63)) * 4 + (g >> 6);
        W0 [dst] = w_hh0[idx];
        W1I[dst] = w_ih1[idx];
        W1H[dst] = w_hh1[idx];
    }
    // zero h buffers (contiguous 5120 floats)
    for (int idx = tid; idx < 5120; idx += NTHR) h0b[idx] = 0.0f;
    // x t=0 into buffer 0 ([k][b])
    if (tid < BTILE*IN_SZ) {
        int b = tid / IN_SZ, k = tid - b*IN_SZ;
        xsm[k*16 + b] = x[(batch0 + b) * (T_LEN*IN_SZ) + k];
    }

    // per-thread w_ih0 rows: this u's 4 gates, its interleaved K-half (k = 2kk+kh)
    float w0r[4][10];
#pragma unroll
    for (int m = 0; m < 4; m++)
#pragma unroll
        for (int kk = 0; kk < 10; kk++)
            w0r[m][kk] = w_ih0[(m*64 + u)*IN_SZ + 2*kk + kh];

    float bs0[4], bs1[4];
#pragma unroll
    for (int m = 0; m < 4; m++) {
        bs0[m] = b_ih0[m*64 + u] + b_hh0[m*64 + u];
        bs1[m] = b_ih1[m*64 + u] + b_hh1[m*64 + u];
    }
    float c0[2] = {0.f, 0.f}, c1[2] = {0.f, 0.f};

    // x prefetch mapping
    const bool xth = tid < BTILE*IN_SZ;
    const int  xb  = xth ? tid / IN_SZ : 0;
    const int  xk  = xth ? tid - xb*IN_SZ : 0;

    __syncthreads();

    for (int t = 0; t < T_LEN; t++) {
        const int cur = t & 1, prv = cur ^ 1;

        float xpre = 0.0f;
        if (xth && t + 1 < T_LEN)
            xpre = x[(batch0 + xb)*(T_LEN*IN_SZ) + (t+1)*IN_SZ + xk];

        const float* h0r = h0b + prv*1280;

        // ================= layer 0 gates =================
        u64 a0[4] = {0,0,0,0}, a1[4] = {0,0,0,0};   // mem-pair0 / mem-pair1

        // x part: k = 2kk + kh
#pragma unroll
        for (int kk = 0; kk < 10; kk++) {
            ulonglong2 xv = *(const ulonglong2*)(xsm + cur*320 + (2*kk + kh)*16 + g4*4);
#pragma unroll
            for (int m = 0; m < 4; m++) {
                u64 w = dup2(w0r[m][kk]);
                fma2(a0[m], w, xv.x);
                fma2(a1[m], w, xv.y);
            }
        }
        // h part: j = 2*j0 + kh
#pragma unroll 8
        for (int j0 = 0; j0 < 32; j0++) {
            int j = 2*j0 + kh;
            float4 w4 = *(const float4*)(W0 + (j << 8) + (u << 2));
            ulonglong2 hv = *(const ulonglong2*)(h0r + j*20 + g4*4);
            u64 p0 = dup2(w4.x), p1 = dup2(w4.y), p2 = dup2(w4.z), p3 = dup2(w4.w);
            fma2(a0[0],p0,hv.x); fma2(a1[0],p0,hv.y);
            fma2(a0[1],p1,hv.x); fma2(a1[1],p1,hv.y);
            fma2(a0[2],p2,hv.x); fma2(a1[2],p2,hv.y);
            fma2(a0[3],p3,hv.x); fma2(a1[3],p3,hv.y);
        }
        // shuffle K-reduce: own = owned mem-pair (index kh), partner holds other K-half
        {
            float hn0, hn1;
            float pre[4][2];
#pragma unroll
            for (int m = 0; m < 4; m++) {
                u64 own = kh ? a1[m] : a0[m];
                u64 oth = kh ? a0[m] : a1[m];
                u64 r = __shfl_xor_sync(0xffffffffu, oth, 16);
                own = add2(own, r);
                unpk(own, pre[m][0], pre[m][1]);
            }
#pragma unroll
            for (int s = 0; s < 2; s++) {
                float iv = sigmoid_f(pre[0][s] + bs0[0]);
                float fv = sigmoid_f(pre[1][s] + bs0[1]);
                float gv = tanh_f   (pre[2][s] + bs0[2]);
                float ov = sigmoid_f(pre[3][s] + bs0[3]);
                float c  = fmaf(fv, c0[s], iv * gv);
                c0[s] = c;
                float hv2 = ov * tanh_f(c);
                if (s == 0) hn0 = hv2; else hn1 = hv2;
            }
            *(float2*)(h0b + cur*1280 + u*20 + bown) = make_float2(hn0, hn1);
        }
        __syncthreads();    // h0(t) ready

        const float* h0n = h0b + cur*1280;
        const float* h1r = h1b + prv*1280;

        // ================= layer 1 gates =================
#pragma unroll
        for (int m = 0; m < 4; m++) { a0[m] = 0ull; a1[m] = 0ull; }

#pragma unroll 4
        for (int j0 = 0; j0 < 32; j0++) {
            int j = 2*j0 + kh;
            float4 wa = *(const float4*)(W1I + (j << 8) + (u << 2));
            float4 wb = *(const float4*)(W1H + (j << 8) + (u << 2));
            ulonglong2 ha = *(const ulonglong2*)(h0n + j*20 + g4*4);
            ulonglong2 hb = *(const ulonglong2*)(h1r + j*20 + g4*4);
            {
                u64 p0 = dup2(wa.x), p1 = dup2(wa.y), p2 = dup2(wa.z), p3 = dup2(wa.w);
                fma2(a0[0],p0,ha.x); fma2(a1[0],p0,ha.y);
                fma2(a0[1],p1,ha.x); fma2(a1[1],p1,ha.y);
                fma2(a0[2],p2,ha.x); fma2(a1[2],p2,ha.y);
                fma2(a0[3],p3,ha.x); fma2(a1[3],p3,ha.y);
            }
            {
                u64 p0 = dup2(wb.x), p1 = dup2(wb.y), p2 = dup2(wb.z), p3 = dup2(wb.w);
                fma2(a0[0],p0,hb.x); fma2(a1[0],p0,hb.y);
                fma2(a0[1],p1,hb.x); fma2(a1[1],p1,hb.y);
                fma2(a0[2],p2,hb.x); fma2(a1[2],p2,hb.y);
                fma2(a0[3],p3,hb.x); fma2(a1[3],p3,hb.y);
            }
        }
        {
            float hn0, hn1;
            float pre[4][2];
#pragma unroll
            for (int m = 0; m < 4; m++) {
                u64 own = kh ? a1[m] : a0[m];
                u64 oth = kh ? a0[m] : a1[m];
                u64 r = __shfl_xor_sync(0xffffffffu, oth, 16);
                own = add2(own, r);
                unpk(own, pre[m][0], pre[m][1]);
            }
#pragma unroll
            for (int s = 0; s < 2; s++) {
                float iv = sigmoid_f(pre[0][s] + bs1[0]);
                float fv = sigmoid_f(pre[1][s] + bs1[1]);
                float gv = tanh_f   (pre[2][s] + bs1[2]);
                float ov = sigmoid_f(pre[3][s] + bs1[3]);
                float c  = fmaf(fv, c1[s], iv * gv);
                c1[s] = c;
                float hv2 = ov * tanh_f(c);
                if (s == 0) hn0 = hv2; else hn1 = hv2;
            }
            *(float2*)(h1b + cur*1280 + u*20 + bown) = make_float2(hn0, hn1);
        }
        // commit prefetched x into the other buffer (read next step by layer 0)
        if (xth && t + 1 < T_LEN)
            xsm[prv*320 + xk*16 + xb] = xpre;
        __syncthreads();    // h1(t), x(t+1) ready
    }

    // ================= output projection (h1 final at buffer (T_LEN-1)&1 = 1) =================
    if (tid < BTILE*5) {
        int b = tid / 5, o = tid - 5*b;
        float s = b_out[o];
        const float* hr = h1b + 1280 + b;   // stride 20 per u
        const float* wr = w_out + o*H;
#pragma unroll 16
        for (int uu = 0; uu < H; uu++) s = fmaf(hr[uu*20], wr[uu], s);
        out[(batch0 + b)*5 + o] = s;
    }
}

extern "C" void kernel_launch(void* const* d_in, const int* in_sizes, int n_in,
                              void* d_out, int out_size) {
    const float* x     = (const float*)d_in[0];
    const float* w_ih0 = (const float*)d_in[1];
    const float* w_hh0 = (const float*)d_in[2];
    const float* b_ih0 = (const float*)d_in[3];
    const float* b_hh0 = (const float*)d_in[4];
    const float* w_ih1 = (const float*)d_in[5];
    const float* w_hh1 = (const float*)d_in[6];
    const float* b_ih1 = (const float*)d_in[7];
    const float* b_hh1 = (const float*)d_in[8];
    const float* w_out = (const float*)d_in[9];
    const float* b_out = (const float*)d_in[10];
    float* out = (float*)d_out;

    cudaFuncSetAttribute(lstm2_kernel, cudaFuncAttributeMaxDynamicSharedMemorySize, SMEM_BYTES);
    lstm2_kernel<<<B_TOT / BTILE, NTHR, SMEM_BYTES>>>(
        x, w_ih0, w_hh0, b_ih0, b_hh0,
        w_ih1, w_hh1, b_ih1, b_hh1,
        w_out, b_out, out);
}

// round 16
// speedup vs baseline: 1.1321x; 1.1306x over previous
#include <cuda_runtime.h>

typedef unsigned long long u64;

#define B_TOT 2048
#define T_LEN 512
#define IN_SZ 20
#define H     64
#define BTILE 16
#define NTHR  512

// ---- smem layout (float offsets) ----
#define OFF_W0   0                  // whh0^T  [64 j][64 u][4 g] = 16384
#define OFF_W1I  16384
#define OFF_W1H  32768
#define OFF_H0   49152              // h0 [2 buf][64 u][20 (16 used)] = 2560
#define OFF_H1   51712              // h1 [2][64][20] = 2560
#define OFF_XS   54272              // x  [2][20 k][16 b] = 640
#define SMEM_FLOATS 54912
#define SMEM_BYTES  (SMEM_FLOATS*4) // 219648 B

__device__ __forceinline__ u64 dup2(float v){ u64 r; asm("mov.b64 %0,{%1,%1};":"=l"(r):"f"(v)); return r; }
__device__ __forceinline__ u64 pk2(float lo, float hi){ u64 r; asm("mov.b64 %0,{%1,%2};":"=l"(r):"f"(lo),"f"(hi)); return r; }
__device__ __forceinline__ void fma2(u64& d, u64 a, u64 b){ asm("fma.rn.f32x2 %0,%1,%2,%0;":"+l"(d):"l"(a),"l"(b)); }
__device__ __forceinline__ u64 add2(u64 a, u64 b){ u64 r; asm("add.rn.f32x2 %0,%1,%2;":"=l"(r):"l"(a),"l"(b)); return r; }
__device__ __forceinline__ void unpk(u64 v, float& lo, float& hi){ asm("mov.b64 {%0,%1},%2;":"=f"(lo),"=f"(hi):"l"(v)); }

__device__ __forceinline__ float sigmoid_f(float v){ return 1.0f/(1.0f+__expf(-v)); }
__device__ __forceinline__ float tanh_f(float v){
    float xx = fmaxf(v, -15.0f);
    float t  = __expf(-2.0f*xx);
    return __fdividef(1.0f - t, 1.0f + t);
}

// reduce one output (2 gate-pairs x 4 batches) over kh via xor-16 butterfly,
// then activate 2 owned batches, update c, return packed h pair.
__device__ __forceinline__ float2 reduce_act(u64 a[2][4], int kh, float* c)
{
    u64 own[2][2];
#pragma unroll
    for (int gp = 0; gp < 2; gp++) {
        u64 o0 = kh ? a[gp][2] : a[gp][0];
        u64 x0 = kh ? a[gp][0] : a[gp][2];
        u64 o1 = kh ? a[gp][3] : a[gp][1];
        u64 x1 = kh ? a[gp][1] : a[gp][3];
        own[gp][0] = add2(o0, __shfl_xor_sync(0xffffffffu, x0, 16));
        own[gp][1] = add2(o1, __shfl_xor_sync(0xffffffffu, x1, 16));
    }
    float h[2];
#pragma unroll
    for (int s = 0; s < 2; s++) {
        float i_, f_, g_, o_;
        unpk(own[0][s], i_, f_);
        unpk(own[1][s], g_, o_);
        float iv = sigmoid_f(i_);
        float fv = sigmoid_f(f_);
        float gv = tanh_f   (g_);
        float ov = sigmoid_f(o_);
        float cc = fmaf(fv, c[s], iv * gv);
        c[s] = cc;
        h[s] = ov * tanh_f(cc);
    }
    return make_float2(h[0], h[1]);
}

__global__ void __launch_bounds__(NTHR,1) lstm2_kernel(
    const float* __restrict__ x,
    const float* __restrict__ w_ih0, const float* __restrict__ w_hh0,
    const float* __restrict__ b_ih0, const float* __restrict__ b_hh0,
    const float* __restrict__ w_ih1, const float* __restrict__ w_hh1,
    const float* __restrict__ b_ih1, const float* __restrict__ b_hh1,
    const float* __restrict__ w_out, const float* __restrict__ b_out,
    float* __restrict__ out)
{
    extern __shared__ float sm[];
    float* W0  = sm + OFF_W0;
    float* W1I = sm + OFF_W1I;
    float* W1H = sm + OFF_W1H;
    float* h0b = sm + OFF_H0;
    float* h1b = sm + OFF_H1;
    float* xsm = sm + OFF_XS;

    const int tid    = threadIdx.x;
    const int lane   = tid & 31;
    const int wid    = tid >> 5;
    const int ul     = lane & 7;
    const int bgl    = (lane >> 3) & 1;
    const int kh     = lane >> 4;          // K-half (lane bit 4)
    const int uh     = wid & 7;
    const int bgo    = wid >> 3;
    const int u      = uh * 8 + ul;        // hidden unit
    const int g4     = bgo * 2 + bgl;      // 4-batch group 0..3
    const int bown   = g4 * 4 + kh * 2;    // first owned batch
    const int batch0 = blockIdx.x * BTILE;

    // ---- weight transpose into smem: dst[(j*64+u)*4 + gate] ----
    for (int idx = tid; idx < 4*H*H; idx += NTHR) {
        int g = idx >> 6, j = idx & 63;
        int dst = ((j << 6) + (g & 63)) * 4 + (g >> 6);
        W0 [dst] = w_hh0[idx];
        W1I[dst] = w_ih1[idx];
        W1H[dst] = w_hh1[idx];
    }
    for (int idx = tid; idx < 5120; idx += NTHR) h0b[idx] = 0.0f;   // h0+h1 both bufs
    // x(0) -> buf0, x(1) -> buf1  ([k][b] transposed)
    if (tid < BTILE*IN_SZ) {
        int b = tid / IN_SZ, k = tid - b*IN_SZ;
        const float* xr = x + (batch0 + b)*(T_LEN*IN_SZ) + k;
        xsm[k*16 + b]       = xr[0];
        xsm[320 + k*16 + b] = xr[IN_SZ];
    }

    // w_ih0 as gate-pairs for this u, interleaved K-half (k = 2kk+kh)
    u64 w0p[2][10];
#pragma unroll
    for (int gp = 0; gp < 2; gp++)
#pragma unroll
        for (int kk = 0; kk < 10; kk++)
            w0p[gp][kk] = pk2(w_ih0[((2*gp  )*64 + u)*IN_SZ + 2*kk + kh],
                              w_ih0[((2*gp+1)*64 + u)*IN_SZ + 2*kk + kh]);

    // bias packed into accumulator init (kh==0 half only; kh==1 inits 0)
    u64 ib0[2], ib1[2];
#pragma unroll
    for (int gp = 0; gp < 2; gp++) {
        u64 p0 = pk2(b_ih0[(2*gp)*64+u] + b_hh0[(2*gp)*64+u],
                     b_ih0[(2*gp+1)*64+u] + b_hh0[(2*gp+1)*64+u]);
        u64 p1 = pk2(b_ih1[(2*gp)*64+u] + b_hh1[(2*gp)*64+u],
                     b_ih1[(2*gp+1)*64+u] + b_hh1[(2*gp+1)*64+u]);
        ib0[gp] = kh ? 0ull : p0;
        ib1[gp] = kh ? 0ull : p1;
    }
    float c0[2] = {0.f, 0.f}, c1[2] = {0.f, 0.f};

    const bool xth = tid < BTILE*IN_SZ;
    const int  xb  = xth ? tid / IN_SZ : 0;
    const int  xk  = xth ? tid - xb*IN_SZ : 0;
    const float* xgp = x + (batch0 + xb)*(T_LEN*IN_SZ) + xk;

    __syncthreads();

    // ================= prologue: L0(0) = act(Wih0 x(0) + b)  (h0(-1)=0) =================
    {
        u64 aL0[2][4];
#pragma unroll
        for (int gp = 0; gp < 2; gp++) { aL0[gp][0]=ib0[gp]; aL0[gp][1]=ib0[gp]; aL0[gp][2]=ib0[gp]; aL0[gp][3]=ib0[gp]; }
#pragma unroll
        for (int kk = 0; kk < 10; kk++) {
            float4 xv = *(const float4*)(xsm + (2*kk + kh)*16 + g4*4);
            u64 d0 = dup2(xv.x), d1 = dup2(xv.y), d2 = dup2(xv.z), d3 = dup2(xv.w);
#pragma unroll
            for (int gp = 0; gp < 2; gp++) {
                u64 w = w0p[gp][kk];
                fma2(aL0[gp][0],w,d0); fma2(aL0[gp][1],w,d1); fma2(aL0[gp][2],w,d2); fma2(aL0[gp][3],w,d3);
            }
        }
        float2 hv = reduce_act(aL0, kh, c0);
        *(float2*)(h0b + 0*1280 + u*20 + bown) = hv;   // h0(0) -> buf0
    }
    __syncthreads();

    // ================= fused phases p=0..510: L1(p) + L0(p+1), ONE barrier =============
    for (int p = 0; p < T_LEN-1; p++) {
        const int cur = p & 1, nxt = cur ^ 1;

        float xpre = 0.0f;
        if (xth && p + 2 < T_LEN) xpre = xgp[(p+2)*IN_SZ];

        u64 aL1[2][4], aL0[2][4];
#pragma unroll
        for (int gp = 0; gp < 2; gp++) {
            aL1[gp][0]=ib1[gp]; aL1[gp][1]=ib1[gp]; aL1[gp][2]=ib1[gp]; aL1[gp][3]=ib1[gp];
            aL0[gp][0]=ib0[gp]; aL0[gp][1]=ib0[gp]; aL0[gp][2]=ib0[gp]; aL0[gp][3]=ib0[gp];
        }

        // x(p+1) part -> L0(p+1)
#pragma unroll
        for (int kk = 0; kk < 10; kk++) {
            float4 xv = *(const float4*)(xsm + nxt*320 + (2*kk + kh)*16 + g4*4);
            u64 d0 = dup2(xv.x), d1 = dup2(xv.y), d2 = dup2(xv.z), d3 = dup2(xv.w);
#pragma unroll
            for (int gp = 0; gp < 2; gp++) {
                u64 w = w0p[gp][kk];
                fma2(aL0[gp][0],w,d0); fma2(aL0[gp][1],w,d1); fma2(aL0[gp][2],w,d2); fma2(aL0[gp][3],w,d3);
            }
        }

        const float* h0r = h0b + cur*1280;   // h0(p)
        const float* h1r = h1b + nxt*1280;   // h1(p-1)

        // fused j-loop: h0 dups shared by W1I (->L1) and W0 (->L0)
#pragma unroll 4
        for (int j0 = 0; j0 < 32; j0++) {
            int j = 2*j0 + kh;
            float4 h0v = *(const float4*)(h0r + j*20 + g4*4);
            u64 d0 = dup2(h0v.x), d1 = dup2(h0v.y), d2 = dup2(h0v.z), d3 = dup2(h0v.w);
            ulonglong2 wi = *(const ulonglong2*)(W1I + (j << 8) + (u << 2));
            fma2(aL1[0][0],wi.x,d0); fma2(aL1[0][1],wi.x,d1); fma2(aL1[0][2],wi.x,d2); fma2(aL1[0][3],wi.x,d3);
            fma2(aL1[1][0],wi.y,d0); fma2(aL1[1][1],wi.y,d1); fma2(aL1[1][2],wi.y,d2); fma2(aL1[1][3],wi.y,d3);
            ulonglong2 w0 = *(const ulonglong2*)(W0 + (j << 8) + (u << 2));
            fma2(aL0[0][0],w0.x,d0); fma2(aL0[0][1],w0.x,d1); fma2(aL0[0][2],w0.x,d2); fma2(aL0[0][3],w0.x,d3);
            fma2(aL0[1][0],w0.y,d0); fma2(aL0[1][1],w0.y,d1); fma2(aL0[1][2],w0.y,d2); fma2(aL0[1][3],w0.y,d3);
            float4 h1v = *(const float4*)(h1r + j*20 + g4*4);
            u64 e0 = dup2(h1v.x), e1 = dup2(h1v.y), e2 = dup2(h1v.z), e3 = dup2(h1v.w);
            ulonglong2 wh = *(const ulonglong2*)(W1H + (j << 8) + (u << 2));
            fma2(aL1[0][0],wh.x,e0); fma2(aL1[0][1],wh.x,e1); fma2(aL1[0][2],wh.x,e2); fma2(aL1[0][3],wh.x,e3);
            fma2(aL1[1][0],wh.y,e0); fma2(aL1[1][1],wh.y,e1); fma2(aL1[1][2],wh.y,e2); fma2(aL1[1][3],wh.y,e3);
        }

        float2 h1v = reduce_act(aL1, kh, c1);
        *(float2*)(h1b + cur*1280 + u*20 + bown) = h1v;     // h1(p)   -> buf p&1
        float2 h0v = reduce_act(aL0, kh, c0);
        *(float2*)(h0b + nxt*1280 + u*20 + bown) = h0v;     // h0(p+1) -> buf (p+1)&1

        if (xth && p + 2 < T_LEN)
            xsm[cur*320 + xk*16 + xb] = xpre;               // x(p+2) -> buf (p+2)&1

        __syncthreads();
    }

    // ================= epilogue: L1(511) =================
    {
        u64 aL1[2][4];
#pragma unroll
        for (int gp = 0; gp < 2; gp++) { aL1[gp][0]=ib1[gp]; aL1[gp][1]=ib1[gp]; aL1[gp][2]=ib1[gp]; aL1[gp][3]=ib1[gp]; }
        const float* h0r = h0b + 1*1280;   // h0(511) (written by p=510, nxt=1)
        const float* h1r = h1b + 0*1280;   // h1(510) (p=510, cur=0)
#pragma unroll 4
        for (int j0 = 0; j0 < 32; j0++) {
            int j = 2*j0 + kh;
            float4 h0v = *(const float4*)(h0r + j*20 + g4*4);
            u64 d0 = dup2(h0v.x), d1 = dup2(h0v.y), d2 = dup2(h0v.z), d3 = dup2(h0v.w);
            ulonglong2 wi = *(const ulonglong2*)(W1I + (j << 8) + (u << 2));
            fma2(aL1[0][0],wi.x,d0); fma2(aL1[0][1],wi.x,d1); fma2(aL1[0][2],wi.x,d2); fma2(aL1[0][3],wi.x,d3);
            fma2(aL1[1][0],wi.y,d0); fma2(aL1[1][1],wi.y,d1); fma2(aL1[1][2],wi.y,d2); fma2(aL1[1][3],wi.y,d3);
            float4 h1v = *(const float4*)(h1r + j*20 + g4*4);
            u64 e0 = dup2(h1v.x), e1 = dup2(h1v.y), e2 = dup2(h1v.z), e3 = dup2(h1v.w);
            ulonglong2 wh = *(const ulonglong2*)(W1H + (j << 8) + (u << 2));
            fma2(aL1[0][0],wh.x,e0); fma2(aL1[0][1],wh.x,e1); fma2(aL1[0][2],wh.x,e2); fma2(aL1[0][3],wh.x,e3);
            fma2(aL1[1][0],wh.y,e0); fma2(aL1[1][1],wh.y,e1); fma2(aL1[1][2],wh.y,e2); fma2(aL1[1][3],wh.y,e3);
        }
        float2 hv = reduce_act(aL1, kh, c1);
        *(float2*)(h1b + 1*1280 + u*20 + bown) = hv;        // h1(511) -> buf1
    }
    __syncthreads();

    // ================= output projection =================
    if (tid < BTILE*5) {
        int b = tid / 5, o = tid - 5*b;
        float s = b_out[o];
        const float* hr = h1b + 1280 + b;   // stride 20 per u
        const float* wr = w_out + o*H;
#pragma unroll 16
        for (int uu = 0; uu < H; uu++) s = fmaf(hr[uu*20], wr[uu], s);
        out[(batch0 + b)*5 + o] = s;
    }
}

extern "C" void kernel_launch(void* const* d_in, const int* in_sizes, int n_in,
                              void* d_out, int out_size) {
    const float* x     = (const float*)d_in[0];
    const float* w_ih0 = (const float*)d_in[1];
    const float* w_hh0 = (const float*)d_in[2];
    const float* b_ih0 = (const float*)d_in[3];
    const float* b_hh0 = (const float*)d_in[4];
    const float* w_ih1 = (const float*)d_in[5];
    const float* w_hh1 = (const float*)d_in[6];
    const float* b_ih1 = (const float*)d_in[7];
    const float* b_hh1 = (const float*)d_in[8];
    const float* w_out = (const float*)d_in[9];
    const float* b_out = (const float*)d_in[10];
    float* out = (float*)d_out;

    cudaFuncSetAttribute(lstm2_kernel, cudaFuncAttributeMaxDynamicSharedMemorySize, SMEM_BYTES);
    lstm2_kernel<<<B_TOT / BTILE, NTHR, SMEM_BYTES>>>(
        x, w_ih0, w_hh0, b_ih0, b_hh0,
        w_ih1, w_hh1, b_ih1, b_hh1,
        w_out, b_out, out);
}